// round 10
// baseline (speedup 1.0000x reference)
#include <cuda_runtime.h>
#include <cstddef>
#include <cstdint>

#define NN0 50000
#define NN1 20000
#define NN2 8000
#define NN3 3200
#define NN4 1300

// ---------------- device scratch (no allocation allowed) ----------------
__device__ float g_x0[NN0 * 32];
__device__ float g_x1[NN1 * 32];
__device__ float g_x2[NN2 * 64];
__device__ float g_x3[NN3 * 128];
__device__ float g_x4[NN4 * 256];
__device__ float g_y [NN0 * 128];
__device__ float g_ta[NN0 * 128];
__device__ float g_tb[NN0 * 128];
__device__ float g_split[4 * 1024 * 1024];
__device__ float g_p1[800 * 512];
__device__ float g_p2[800 * 512];
__device__ float g_mean[2 * 512];
__device__ float g_istd[2 * 512];

// ---------------- tf32 helpers -------------------------------------------
__device__ __forceinline__ void split_tf32(float x, uint32_t& h, uint32_t& l)
{
    uint32_t u;
    asm("cvt.rna.tf32.f32 %0, %1;" : "=r"(u) : "f"(x));
    h = u;
    l = __float_as_uint(x - __uint_as_float(u));
}

__device__ __forceinline__ void mma_tf32(float* c, const uint32_t* a, const uint32_t* b)
{
    asm volatile(
        "mma.sync.aligned.m16n8k8.row.col.f32.tf32.tf32.f32 "
        "{%0,%1,%2,%3}, {%4,%5,%6,%7}, {%8,%9}, {%0,%1,%2,%3};\n"
        : "+f"(c[0]), "+f"(c[1]), "+f"(c[2]), "+f"(c[3])
        : "r"(a[0]), "r"(a[1]), "r"(a[2]), "r"(a[3]),
          "r"(b[0]), "r"(b[1]));
}

// ---------------- TF32x3 tensor-core gather-GEMM --------------------------
// out[M,Cout] = sum_{k in [k0,k1)} X[nbr[m,k]] @ W[k]  (nbr==null -> identity)
// Block tile 64 x TBN, 256 threads (8 warps, 4M x 2N). fp32 staged in smem
// ONCE; hi/lo tf32 split done in registers at fragment-load time (fma/alu
// pipes, idle). 3 mma per product for near-fp32 accuracy.
template<int TBN>
__global__ __launch_bounds__(256)
void gmma_t(const float* __restrict__ X,
            const int*   __restrict__ nbr,
            const float* __restrict__ W,
            const float* __restrict__ bias,
            float* __restrict__ out,
            int M, int Cin, int Cout, int Koff, int k0, int k1, int doRelu)
{
    constexpr int TBM = 64;
    constexpr int PA  = 20;                 // A pitch ([m][k] layout, 16+4)
    constexpr int PB  = TBN + 8;            // B pitch ([k][n] layout)
    constexpr int NF  = TBN / 16;           // n-frags per warp
    constexpr int BV  = (4 * TBN + 255) / 256;

    extern __shared__ float sm[];
    float* As = sm;                           // [2][TBM][PA]  fp32
    float* Bs = As + 2 * TBM * PA;            // [2][16][PB]   fp32
    int*   rows = (int*)(Bs + 2 * 16 * PB);   // [nk][TBM], nk <= 27

    const int tid  = threadIdx.x;
    const int m0   = blockIdx.y * TBM;
    const int n0   = blockIdx.x * TBN;
    const int warp = tid >> 5, lane = tid & 31;
    const int wm = warp >> 1, wn = warp & 1;
    const int lg = lane >> 2, lt = lane & 3;

    const int nk      = k1 - k0;
    const int kchunks = (Cin + 15) >> 4;
    const int nIter   = nk * kchunks;
    const bool bVec = (Cout % 4 == 0) && ((((uintptr_t)W) & 15u) == 0u)
                      && (((Cin * Cout) & 3) == 0);

    for (int idx = tid; idx < nk * TBM; idx += 256) {
        int kk = idx / TBM, mi = idx - kk * TBM;
        int m  = m0 + mi;
        rows[kk * TBM + mi] = (m < M) ? (nbr ? nbr[(size_t)m * Koff + k0 + kk] : m) : 0;
    }
    __syncthreads();

    float acc[NF][4];
    #pragma unroll
    for (int f = 0; f < NF; ++f)
        #pragma unroll
        for (int j = 0; j < 4; ++j) acc[f][j] = 0.f;

    float4 aR;
    float4 bR[BV];
    const int amI = tid >> 2;            // A row this thread stages
    const int acI = (tid & 3) << 2;      // A channel group base

    auto loadStage = [&](int t) {
        int k   = t / kchunks;
        int cc  = t - k * kchunks;
        int ci0 = cc << 4;
        {
            int c = ci0 + acI;
            float4 v = make_float4(0.f, 0.f, 0.f, 0.f);
            if (c < Cin)
                v = *reinterpret_cast<const float4*>(
                        X + (size_t)rows[k * TBM + amI] * Cin + c);
            aR = v;
        }
        const float* Wk = W + (size_t)(k0 + k) * Cin * Cout;
        if (bVec) {
            #pragma unroll
            for (int v = 0; v < BV; ++v) {
                int idx = tid + v * 256;
                float4 val = make_float4(0.f, 0.f, 0.f, 0.f);
                if (idx < 4 * TBN) {
                    int ni = (idx % (TBN / 4)) * 4;
                    int ki = idx / (TBN / 4);
                    int c  = ci0 + ki;
                    int n  = n0 + ni;
                    if (c < Cin && n < Cout)
                        val = *reinterpret_cast<const float4*>(
                                  Wk + (size_t)c * Cout + n);
                }
                bR[v] = val;
            }
        } else {
            #pragma unroll
            for (int v = 0; v < BV; ++v) {
                int idx = tid + v * 256;
                float4 val = make_float4(0.f, 0.f, 0.f, 0.f);
                if (idx < 4 * TBN) {
                    int ni = (idx % (TBN / 4)) * 4;
                    int ki = idx / (TBN / 4);
                    int c  = ci0 + ki;
                    if (c < Cin) {
                        const float* p = Wk + (size_t)c * Cout;
                        int n = n0 + ni;
                        if (n + 0 < Cout) val.x = p[n + 0];
                        if (n + 1 < Cout) val.y = p[n + 1];
                        if (n + 2 < Cout) val.z = p[n + 2];
                        if (n + 3 < Cout) val.w = p[n + 3];
                    }
                }
                bR[v] = val;
            }
        }
    };

    auto storeStage = [&](int s) {
        *reinterpret_cast<float4*>(As + (s * TBM + amI) * PA + acI) = aR;
        #pragma unroll
        for (int v = 0; v < BV; ++v) {
            int idx = tid + v * 256;
            if (idx < 4 * TBN) {
                int ni = (idx % (TBN / 4)) * 4;
                int ki = idx / (TBN / 4);
                *reinterpret_cast<float4*>(Bs + (s * 16 + ki) * PB + ni) = bR[v];
            }
        }
    };

    auto computeStage = [&](int s) {
        #pragma unroll
        for (int ks = 0; ks < 2; ++ks) {
            const int cb = ks * 8;
            const float* aP = As + (s * TBM) * PA;
            const int mA = wm * 16 + lg;
            const int cA = cb + lt;
            uint32_t ah[4], al[4];
            split_tf32(aP[(mA    ) * PA + cA    ], ah[0], al[0]);
            split_tf32(aP[(mA + 8) * PA + cA    ], ah[1], al[1]);
            split_tf32(aP[(mA    ) * PA + cA + 4], ah[2], al[2]);
            split_tf32(aP[(mA + 8) * PA + cA + 4], ah[3], al[3]);
            const float* bP = Bs + (s * 16) * PB;
            #pragma unroll
            for (int f = 0; f < NF; ++f) {
                const int nB = wn * (TBN / 2) + f * 8 + lg;
                const int cB = cb + lt;
                uint32_t bh[2], bl[2];
                split_tf32(bP[(cB    ) * PB + nB], bh[0], bl[0]);
                split_tf32(bP[(cB + 4) * PB + nB], bh[1], bl[1]);
                mma_tf32(acc[f], al, bh);
                mma_tf32(acc[f], ah, bl);
                mma_tf32(acc[f], ah, bh);
            }
        }
    };

    loadStage(0);
    storeStage(0);
    __syncthreads();

    for (int t = 0; t < nIter; ++t) {
        int cur = t & 1;
        if (t + 1 < nIter) loadStage(t + 1);
        computeStage(cur);
        if (t + 1 < nIter) storeStage(cur ^ 1);
        __syncthreads();
    }

    // ---- epilogue ----
    #pragma unroll
    for (int f = 0; f < NF; ++f) {
        int nb  = n0 + wn * (TBN / 2) + f * 8;
        int c0i = nb + lt * 2;
        int r   = m0 + wm * 16 + lg;
        float b0v = 0.f, b1v = 0.f;
        if (bias) {
            if (c0i     < Cout) b0v = bias[c0i];
            if (c0i + 1 < Cout) b1v = bias[c0i + 1];
        }
        if (r < M) {
            if (c0i < Cout) {
                float v = acc[f][0] + b0v;
                if (doRelu) v = fmaxf(v, 0.f);
                out[(size_t)r * Cout + c0i] = v;
            }
            if (c0i + 1 < Cout) {
                float v = acc[f][1] + b1v;
                if (doRelu) v = fmaxf(v, 0.f);
                out[(size_t)r * Cout + c0i + 1] = v;
            }
        }
        int r2 = r + 8;
        if (r2 < M) {
            if (c0i < Cout) {
                float v = acc[f][2] + b0v;
                if (doRelu) v = fmaxf(v, 0.f);
                out[(size_t)r2 * Cout + c0i] = v;
            }
            if (c0i + 1 < Cout) {
                float v = acc[f][3] + b1v;
                if (doRelu) v = fmaxf(v, 0.f);
                out[(size_t)r2 * Cout + c0i + 1] = v;
            }
        }
    }
}

// ordered deterministic sum of S split partials
__global__ void reduce_split_kernel(const float* __restrict__ buf,
                                    float* __restrict__ out,
                                    long long MN, int S)
{
    long long i = (long long)blockIdx.x * blockDim.x + threadIdx.x;
    if (i >= MN) return;
    float s = 0.f;
    for (int k = 0; k < S; ++k) s += buf[(size_t)k * MN + i];
    out[i] = s;
}

// ---------------- BN stats (deterministic two-phase) ----------------------
#define STAT_ROWS 256
__global__ void bn_stats_kernel(const float* __restrict__ x, int M, int C,
                                float* __restrict__ p1, float* __restrict__ p2)
{
    const int r0   = blockIdx.x * STAT_ROWS;
    const int rend = min(r0 + STAT_ROWS, M);
    const int c0 = threadIdx.x;
    const int c1 = threadIdx.x + 256;
    float a0 = 0.f, q0 = 0.f, a1 = 0.f, q1 = 0.f;
    for (int r = r0; r < rend; ++r) {
        const float* row = x + (size_t)r * C;
        if (c0 < C) { float v = row[c0]; a0 += v; q0 += v * v; }
        if (c1 < C) { float v = row[c1]; a1 += v; q1 += v * v; }
    }
    float* o1 = p1 + (size_t)blockIdx.x * 512;
    float* o2 = p2 + (size_t)blockIdx.x * 512;
    if (c0 < C) { o1[c0] = a0; o2[c0] = q0; }
    if (c1 < C) { o1[c1] = a1; o2[c1] = q1; }
}

__global__ void bn_finalize_kernel(const float* __restrict__ p1,
                                   const float* __restrict__ p2,
                                   int nblk, int M, int C,
                                   float* __restrict__ mean,
                                   float* __restrict__ istd)
{
    int warp = (blockIdx.x * blockDim.x + threadIdx.x) >> 5;
    int lane = threadIdx.x & 31;
    if (warp >= C) return;
    float s1 = 0.f, s2 = 0.f;
    for (int b = lane; b < nblk; b += 32) {
        s1 += p1[(size_t)b * 512 + warp];
        s2 += p2[(size_t)b * 512 + warp];
    }
    #pragma unroll
    for (int o = 16; o > 0; o >>= 1) {
        s1 += __shfl_down_sync(0xffffffffu, s1, o);
        s2 += __shfl_down_sync(0xffffffffu, s2, o);
    }
    if (lane == 0) {
        float m = s1 / (float)M;
        float v = s2 / (float)M - m * m;
        mean[warp] = m;
        istd[warp] = rsqrtf(v + 1e-5f);
    }
}

// mode 0: relu((a-m0)*i0); 1: relu(bn(a)+b); 2: relu(bn(a)+bn2(b))
__global__ void bn_apply_kernel(const float* __restrict__ a,
                                const float* __restrict__ b,
                                const float* __restrict__ m0, const float* __restrict__ i0,
                                const float* __restrict__ m1, const float* __restrict__ i1,
                                float* __restrict__ out, int M, int C, int mode)
{
    size_t i = (size_t)blockIdx.x * blockDim.x + threadIdx.x;
    size_t total = (size_t)M * C;
    if (i >= total) return;
    int c = (int)(i % (size_t)C);
    float v = (a[i] - m0[c]) * i0[c];
    if (mode == 1)      v += b[i];
    else if (mode == 2) v += (b[i] - m1[c]) * i1[c];
    out[i] = fmaxf(v, 0.f);
}

// ---------------- transposed conv ----------------------------------------
__global__ void deconv_kernel(const float* __restrict__ X,
                              const int* __restrict__ parent,
                              const int* __restrict__ koff,
                              const float* __restrict__ W,
                              float* __restrict__ out,
                              int M, int Cin, int Cout)
{
    __shared__ float xs[256];
    const int m = blockIdx.x;
    const int p = parent[m];
    const int o = koff[m];
    for (int c = threadIdx.x; c < Cin; c += blockDim.x)
        xs[c] = X[(size_t)p * Cin + c];
    __syncthreads();
    const float* Wk = W + (size_t)o * Cin * Cout;
    for (int n = threadIdx.x; n < Cout; n += blockDim.x) {
        float acc = 0.f;
        #pragma unroll 4
        for (int ci = 0; ci < Cin; ++ci)
            acc += xs[ci] * Wk[(size_t)ci * Cout + n];
        out[(size_t)m * Cout + n] = acc;
    }
}

__global__ void concat_kernel(const float* __restrict__ a, const float* __restrict__ b,
                              float* __restrict__ out, int M, int Ca, int Cb)
{
    size_t i = (size_t)blockIdx.x * blockDim.x + threadIdx.x;
    const int C = Ca + Cb;
    size_t total = (size_t)M * C;
    if (i >= total) return;
    int r = (int)(i / (size_t)C);
    int c = (int)(i % (size_t)C);
    out[i] = (c < Ca) ? a[(size_t)r * Ca + c] : b[(size_t)r * Cb + (c - Ca)];
}

// ---------------- host-side orchestration --------------------------------
static float *TA, *TB, *Y, *X0, *X1, *X2, *X3, *X4, *SPL, *P1, *P2, *MEAN, *ISTD;
static const float* gP;
static size_t gOff;

static inline const float* takeP(size_t n) { const float* w = gP + gOff; gOff += n; return w; }
static inline int cdiv(int a, int b) { return (a + b - 1) / b; }

static inline size_t gmma_smem(int TBN)
{
    int PB = TBN + 8;
    size_t floats = (size_t)2 * 64 * 20 + (size_t)2 * 16 * PB + 27 * 64;
    return floats * 4;
}

static void launch_gmma(int TBN, dim3 grid,
                        const float* X, const int* nbr, const float* W,
                        const float* bias, float* out,
                        int M, int Cin, int Cout, int K, int k0, int k1, int relu)
{
    size_t sh = gmma_smem(TBN);
    switch (TBN) {
    case 32: gmma_t<32><<<grid, 256, sh>>>(X, nbr, W, bias, out, M, Cin, Cout, K, k0, k1, relu); break;
    case 96: gmma_t<96><<<grid, 256, sh>>>(X, nbr, W, bias, out, M, Cin, Cout, K, k0, k1, relu); break;
    default: gmma_t<64><<<grid, 256, sh>>>(X, nbr, W, bias, out, M, Cin, Cout, K, k0, k1, relu); break;
    }
}

static void run_conv(const float* X, const int* nbr, const float* W, float* out,
                     int M, int Cin, int Cout, int K,
                     const float* bias = nullptr, int relu = 0)
{
    int TBN = (Cout == 96) ? 96 : (Cout <= 32 ? 32 : 64);
    dim3 grid(cdiv(Cout, TBN), cdiv(M, 64));
    int blocks = grid.x * grid.y;

    int S = 1, kper = K;
    if (nbr && K > 1 && blocks < 296) {
        S = (296 + blocks - 1) / blocks;
        if (S > K) S = K;
        kper = (K + S - 1) / S;
        S = (K + kper - 1) / kper;
    }
    if (S == 1) {
        launch_gmma(TBN, grid, X, nbr, W, bias, out, M, Cin, Cout, K, 0, K, relu);
    } else {
        long long MN = (long long)M * Cout;
        for (int s = 0; s < S; ++s) {
            int k0 = s * kper;
            int k1 = k0 + kper; if (k1 > K) k1 = K;
            launch_gmma(TBN, grid, X, nbr, W, nullptr, SPL + (size_t)s * MN,
                        M, Cin, Cout, K, k0, k1, 0);
        }
        reduce_split_kernel<<<(unsigned)((MN + 255) / 256), 256>>>(SPL, out, MN, S);
    }
}

static void run_bn(const float* a, int M, int C, int slot)
{
    int nb = cdiv(M, STAT_ROWS);
    bn_stats_kernel<<<nb, 256>>>(a, M, C, P1, P2);
    bn_finalize_kernel<<<cdiv(C * 32, 256), 256>>>(P1, P2, nb, M, C,
                                                   MEAN + slot * 512, ISTD + slot * 512);
}

static void run_apply(const float* a, const float* b, float* out, int M, int C, int mode)
{
    size_t total = (size_t)M * C;
    bn_apply_kernel<<<(unsigned)((total + 255) / 256), 256>>>(
        a, b, MEAN, ISTD, MEAN + 512, ISTD + 512, out, M, C, mode);
}

static void cbr(const float* x, const int* nbr, int M, int Cin, int Cout, int K, float* out)
{
    const float* w = takeP((size_t)K * Cin * Cout);
    run_conv(x, nbr, w, TA, M, Cin, Cout, K);
    run_bn(TA, M, Cout, 0);
    run_apply(TA, nullptr, out, M, Cout, 0);
}

static void resblock(const float* x, const int* nbr, int M, int ci, int co, float* out)
{
    const float* w1 = takeP((size_t)27 * ci * co);
    const float* w2 = takeP((size_t)27 * co * co);
    run_conv(x, nbr, w1, TA, M, ci, co, 27);
    run_bn(TA, M, co, 0);
    run_apply(TA, nullptr, TB, M, co, 0);
    run_conv(TB, nbr, w2, TA, M, co, co, 27);
    run_bn(TA, M, co, 0);
    if (ci != co) {
        const float* ws = takeP((size_t)ci * co);
        run_conv(x, nullptr, ws, TB, M, ci, co, 1);
        run_bn(TB, M, co, 1);
        run_apply(TA, TB, out, M, co, 2);
    } else {
        run_apply(TA, x, out, M, co, 1);
    }
}

static void up_block(const float* x, const int* par, const int* off, int M,
                     int Cin, int Cout, const float* skip, int Cskip, float* out)
{
    const float* w = takeP((size_t)8 * Cin * Cout);
    deconv_kernel<<<M, 128>>>(x, par, off, w, TA, M, Cin, Cout);
    run_bn(TA, M, Cout, 0);
    run_apply(TA, nullptr, TB, M, Cout, 0);
    size_t total = (size_t)M * (Cout + Cskip);
    concat_kernel<<<(unsigned)((total + 255) / 256), 256>>>(TB, skip, out, M, Cout, Cskip);
}

extern "C" void kernel_launch(void* const* d_in, const int* in_sizes, int n_in,
                              void* d_out, int out_size)
{
    const float* x    = (const float*)d_in[0];
    const int* nbr0   = (const int*)d_in[1];
    const int* nbr1   = (const int*)d_in[2];
    const int* nbr2   = (const int*)d_in[3];
    const int* nbr3   = (const int*)d_in[4];
    const int* nbr4   = (const int*)d_in[5];
    const int* d1     = (const int*)d_in[6];
    const int* d2     = (const int*)d_in[7];
    const int* d3     = (const int*)d_in[8];
    const int* d4     = (const int*)d_in[9];
    const int* u1p    = (const int*)d_in[10];
    const int* u1o    = (const int*)d_in[11];
    const int* u2p    = (const int*)d_in[12];
    const int* u2o    = (const int*)d_in[13];
    const int* u3p    = (const int*)d_in[14];
    const int* u3o    = (const int*)d_in[15];
    const int* u4p    = (const int*)d_in[16];
    const int* u4o    = (const int*)d_in[17];
    gP = (const float*)d_in[18];
    gOff = 0;

    cudaGetSymbolAddress((void**)&X0,   g_x0);
    cudaGetSymbolAddress((void**)&X1,   g_x1);
    cudaGetSymbolAddress((void**)&X2,   g_x2);
    cudaGetSymbolAddress((void**)&X3,   g_x3);
    cudaGetSymbolAddress((void**)&X4,   g_x4);
    cudaGetSymbolAddress((void**)&Y,    g_y);
    cudaGetSymbolAddress((void**)&TA,   g_ta);
    cudaGetSymbolAddress((void**)&TB,   g_tb);
    cudaGetSymbolAddress((void**)&SPL,  g_split);
    cudaGetSymbolAddress((void**)&P1,   g_p1);
    cudaGetSymbolAddress((void**)&P2,   g_p2);
    cudaGetSymbolAddress((void**)&MEAN, g_mean);
    cudaGetSymbolAddress((void**)&ISTD, g_istd);

    // ---- stem (N0) ----
    cbr(x,  nbr0, NN0, 4,  32, 27, X0);
    cbr(X0, nbr0, NN0, 32, 32, 27, X0);

    // ---- stage1 (N1) ----
    cbr(X0, d1, NN1, 32, 32, 8, Y);
    resblock(Y, nbr1, NN1, 32, 32, Y);
    resblock(Y, nbr1, NN1, 32, 32, X1);

    // ---- stage2 (N2) ----
    cbr(X1, d2, NN2, 32, 32, 8, Y);
    resblock(Y, nbr2, NN2, 32, 64, Y);
    resblock(Y, nbr2, NN2, 64, 64, X2);

    // ---- stage3 (N3) ----
    cbr(X2, d3, NN3, 64, 64, 8, Y);
    resblock(Y, nbr3, NN3, 64, 128, Y);
    resblock(Y, nbr3, NN3, 128, 128, X3);

    // ---- stage4 (N4) ----
    cbr(X3, d4, NN4, 128, 128, 8, Y);
    resblock(Y, nbr4, NN4, 128, 256, Y);
    resblock(Y, nbr4, NN4, 256, 256, X4);

    // ---- up1 (N3) ----
    up_block(X4, u1p, u1o, NN3, 256, 256, X3, 128, Y);
    resblock(Y, nbr3, NN3, 384, 256, Y);
    resblock(Y, nbr3, NN3, 256, 256, Y);

    // ---- up2 (N2) ----
    up_block(Y, u2p, u2o, NN2, 256, 128, X2, 64, Y);
    resblock(Y, nbr2, NN2, 192, 128, Y);
    resblock(Y, nbr2, NN2, 128, 128, Y);

    // ---- up3 (N1) ----
    up_block(Y, u3p, u3o, NN1, 128, 96, X1, 32, Y);
    resblock(Y, nbr1, NN1, 128, 96, Y);
    resblock(Y, nbr1, NN1, 96, 96, Y);

    // ---- up4 (N0) ----
    up_block(Y, u4p, u4o, NN0, 96, 96, X0, 32, Y);
    resblock(Y, nbr0, NN0, 128, 96, Y);
    resblock(Y, nbr0, NN0, 96, 96, Y);

    // ---- head ----
    const float* wc = takeP((size_t)96 * 19);
    const float* bc = takeP(19);
    const float* w1 = takeP((size_t)96 * 96);
    const float* b1 = takeP(96);
    const float* w2 = takeP((size_t)96 * 128);
    const float* b2 = takeP(128);

    float* out = (float*)d_out;
    run_conv(Y, nullptr, wc, out, NN0, 96, 19, 1, bc, 0);
    run_conv(Y,  nullptr, w1, TA, NN0, 96, 96, 1, b1, 1);
    run_conv(TA, nullptr, w2, out + (size_t)NN0 * 19, NN0, 96, 128, 1, b2, 0);
}

// round 11
// speedup vs baseline: 1.0875x; 1.0875x over previous
#include <cuda_runtime.h>
#include <cstddef>
#include <cstdint>

#define NN0 50000
#define NN1 20000
#define NN2 8000
#define NN3 3200
#define NN4 1300

// ---------------- device scratch (no allocation allowed) ----------------
__device__ float g_x0[NN0 * 32];
__device__ float g_x1[NN1 * 32];
__device__ float g_x2[NN2 * 64];
__device__ float g_x3[NN3 * 128];
__device__ float g_x4[NN4 * 256];
__device__ float g_y [NN0 * 128];
__device__ float g_ta[NN0 * 128];
__device__ float g_tb[NN0 * 128];
__device__ float g_split[4 * 1024 * 1024];
__device__ float g_p1[800 * 512];
__device__ float g_p2[800 * 512];
__device__ float g_mean[2 * 512];
__device__ float g_istd[2 * 512];

// ---------------- tf32 helpers -------------------------------------------
__device__ __forceinline__ void split_tf32(float x, uint32_t& h, uint32_t& l)
{
    uint32_t u;
    asm("cvt.rna.tf32.f32 %0, %1;" : "=r"(u) : "f"(x));
    h = u;
    l = __float_as_uint(x - __uint_as_float(u));
}

__device__ __forceinline__ void mma_tf32(float* c, const uint32_t* a, const uint32_t* b)
{
    asm volatile(
        "mma.sync.aligned.m16n8k8.row.col.f32.tf32.tf32.f32 "
        "{%0,%1,%2,%3}, {%4,%5,%6,%7}, {%8,%9}, {%0,%1,%2,%3};\n"
        : "+f"(c[0]), "+f"(c[1]), "+f"(c[2]), "+f"(c[3])
        : "r"(a[0]), "r"(a[1]), "r"(a[2]), "r"(a[3]),
          "r"(b[0]), "r"(b[1]));
}

// ---------------- TF32x3 tensor-core gather-GEMM (BK=32) -------------------
// out[M,Cout] = sum_{k in [k0,k1)} X[nbr[m,k]] @ W[k]  (nbr==null -> identity)
// Block tile 64 x TBN, 256 threads (8 warps, 4M x 2N). fp32 staged in smem;
// hi/lo tf32 split in registers at fragment-load. 32-deep K chunk per stage
// (4 mma k-steps) to amortize barriers.
template<int TBN>
__global__ __launch_bounds__(256)
void gmma_t(const float* __restrict__ X,
            const int*   __restrict__ nbr,
            const float* __restrict__ W,
            const float* __restrict__ bias,
            float* __restrict__ out,
            int M, int Cin, int Cout, int Koff, int k0, int k1, int doRelu)
{
    constexpr int TBM = 64;
    constexpr int BKC = 32;                 // K-chunk per stage
    constexpr int PA  = BKC + 4;            // A pitch ([m][k] layout)
    constexpr int PB  = TBN + 8;            // B pitch ([k][n] layout)
    constexpr int NF  = TBN / 16;           // n-frags per warp
    constexpr int BV  = (8 * TBN + 255) / 256;   // B float4 tasks / thread

    extern __shared__ float sm[];
    float* As = sm;                           // [2][TBM][PA]  fp32
    float* Bs = As + 2 * TBM * PA;            // [2][BKC][PB]  fp32
    int*   rows = (int*)(Bs + 2 * BKC * PB);  // [nk][TBM], nk <= 27

    const int tid  = threadIdx.x;
    const int m0   = blockIdx.y * TBM;
    const int n0   = blockIdx.x * TBN;
    const int warp = tid >> 5, lane = tid & 31;
    const int wm = warp >> 1, wn = warp & 1;
    const int lg = lane >> 2, lt = lane & 3;

    const int nk      = k1 - k0;
    const int kchunks = (Cin + BKC - 1) / BKC;
    const int nIter   = nk * kchunks;
    const bool bVec = (Cout % 4 == 0) && ((((uintptr_t)W) & 15u) == 0u)
                      && (((Cin * Cout) & 3) == 0);

    for (int idx = tid; idx < nk * TBM; idx += 256) {
        int kk = idx / TBM, mi = idx - kk * TBM;
        int m  = m0 + mi;
        rows[kk * TBM + mi] = (m < M) ? (nbr ? nbr[(size_t)m * Koff + k0 + kk] : m) : 0;
    }
    __syncthreads();

    float acc[NF][4];
    #pragma unroll
    for (int f = 0; f < NF; ++f)
        #pragma unroll
        for (int j = 0; j < 4; ++j) acc[f][j] = 0.f;

    float4 aR[2];          // A: 512 float4 tasks / 256 threads
    float4 bR[BV];

    auto loadStage = [&](int t) {
        int k   = t / kchunks;
        int cc  = t - k * kchunks;
        int ci0 = cc * BKC;
        #pragma unroll
        for (int v = 0; v < 2; ++v) {
            int task = tid + v * 256;        // < 512
            int mi = task >> 3;
            int cg = (task & 7) << 2;
            int c  = ci0 + cg;
            float4 val = make_float4(0.f, 0.f, 0.f, 0.f);
            if (c < Cin)
                val = *reinterpret_cast<const float4*>(
                          X + (size_t)rows[k * TBM + mi] * Cin + c);
            aR[v] = val;
        }
        const float* Wk = W + (size_t)(k0 + k) * Cin * Cout;
        if (bVec) {
            #pragma unroll
            for (int v = 0; v < BV; ++v) {
                int idx = tid + v * 256;
                float4 val = make_float4(0.f, 0.f, 0.f, 0.f);
                if (idx < 8 * TBN) {
                    int ni = (idx % (TBN / 4)) * 4;
                    int ki = idx / (TBN / 4);
                    int c  = ci0 + ki;
                    int n  = n0 + ni;
                    if (c < Cin && n < Cout)
                        val = *reinterpret_cast<const float4*>(
                                  Wk + (size_t)c * Cout + n);
                }
                bR[v] = val;
            }
        } else {
            #pragma unroll
            for (int v = 0; v < BV; ++v) {
                int idx = tid + v * 256;
                float4 val = make_float4(0.f, 0.f, 0.f, 0.f);
                if (idx < 8 * TBN) {
                    int ni = (idx % (TBN / 4)) * 4;
                    int ki = idx / (TBN / 4);
                    int c  = ci0 + ki;
                    if (c < Cin) {
                        const float* p = Wk + (size_t)c * Cout;
                        int n = n0 + ni;
                        if (n + 0 < Cout) val.x = p[n + 0];
                        if (n + 1 < Cout) val.y = p[n + 1];
                        if (n + 2 < Cout) val.z = p[n + 2];
                        if (n + 3 < Cout) val.w = p[n + 3];
                    }
                }
                bR[v] = val;
            }
        }
    };

    auto storeStage = [&](int s) {
        #pragma unroll
        for (int v = 0; v < 2; ++v) {
            int task = tid + v * 256;
            int mi = task >> 3;
            int cg = (task & 7) << 2;
            *reinterpret_cast<float4*>(As + (s * TBM + mi) * PA + cg) = aR[v];
        }
        #pragma unroll
        for (int v = 0; v < BV; ++v) {
            int idx = tid + v * 256;
            if (idx < 8 * TBN) {
                int ni = (idx % (TBN / 4)) * 4;
                int ki = idx / (TBN / 4);
                *reinterpret_cast<float4*>(Bs + (s * BKC + ki) * PB + ni) = bR[v];
            }
        }
    };

    auto computeStage = [&](int s) {
        #pragma unroll
        for (int ks = 0; ks < 4; ++ks) {
            const int cb = ks * 8;
            const float* aP = As + (s * TBM) * PA;
            const int mA = wm * 16 + lg;
            const int cA = cb + lt;
            uint32_t ah[4], al[4];
            split_tf32(aP[(mA    ) * PA + cA    ], ah[0], al[0]);
            split_tf32(aP[(mA + 8) * PA + cA    ], ah[1], al[1]);
            split_tf32(aP[(mA    ) * PA + cA + 4], ah[2], al[2]);
            split_tf32(aP[(mA + 8) * PA + cA + 4], ah[3], al[3]);
            const float* bP = Bs + (s * BKC) * PB;
            #pragma unroll
            for (int f = 0; f < NF; ++f) {
                const int nB = wn * (TBN / 2) + f * 8 + lg;
                const int cB = cb + lt;
                uint32_t bh[2], bl[2];
                split_tf32(bP[(cB    ) * PB + nB], bh[0], bl[0]);
                split_tf32(bP[(cB + 4) * PB + nB], bh[1], bl[1]);
                mma_tf32(acc[f], al, bh);
                mma_tf32(acc[f], ah, bl);
                mma_tf32(acc[f], ah, bh);
            }
        }
    };

    loadStage(0);
    storeStage(0);
    __syncthreads();

    for (int t = 0; t < nIter; ++t) {
        int cur = t & 1;
        if (t + 1 < nIter) loadStage(t + 1);
        computeStage(cur);
        if (t + 1 < nIter) storeStage(cur ^ 1);
        __syncthreads();
    }

    // ---- epilogue ----
    #pragma unroll
    for (int f = 0; f < NF; ++f) {
        int nb  = n0 + wn * (TBN / 2) + f * 8;
        int c0i = nb + lt * 2;
        int r   = m0 + wm * 16 + lg;
        float b0v = 0.f, b1v = 0.f;
        if (bias) {
            if (c0i     < Cout) b0v = bias[c0i];
            if (c0i + 1 < Cout) b1v = bias[c0i + 1];
        }
        if (r < M) {
            if (c0i < Cout) {
                float v = acc[f][0] + b0v;
                if (doRelu) v = fmaxf(v, 0.f);
                out[(size_t)r * Cout + c0i] = v;
            }
            if (c0i + 1 < Cout) {
                float v = acc[f][1] + b1v;
                if (doRelu) v = fmaxf(v, 0.f);
                out[(size_t)r * Cout + c0i + 1] = v;
            }
        }
        int r2 = r + 8;
        if (r2 < M) {
            if (c0i < Cout) {
                float v = acc[f][2] + b0v;
                if (doRelu) v = fmaxf(v, 0.f);
                out[(size_t)r2 * Cout + c0i] = v;
            }
            if (c0i + 1 < Cout) {
                float v = acc[f][3] + b1v;
                if (doRelu) v = fmaxf(v, 0.f);
                out[(size_t)r2 * Cout + c0i + 1] = v;
            }
        }
    }
}

// ordered deterministic sum of S split partials
__global__ void reduce_split_kernel(const float* __restrict__ buf,
                                    float* __restrict__ out,
                                    long long MN, int S)
{
    long long i = (long long)blockIdx.x * blockDim.x + threadIdx.x;
    if (i >= MN) return;
    float s = 0.f;
    for (int k = 0; k < S; ++k) s += buf[(size_t)k * MN + i];
    out[i] = s;
}

// ---------------- BN stats (deterministic two-phase) ----------------------
#define STAT_ROWS 256
__global__ void bn_stats_kernel(const float* __restrict__ x, int M, int C,
                                float* __restrict__ p1, float* __restrict__ p2)
{
    const int r0   = blockIdx.x * STAT_ROWS;
    const int rend = min(r0 + STAT_ROWS, M);
    const int c0 = threadIdx.x;
    const int c1 = threadIdx.x + 256;
    float a0 = 0.f, q0 = 0.f, a1 = 0.f, q1 = 0.f;
    for (int r = r0; r < rend; ++r) {
        const float* row = x + (size_t)r * C;
        if (c0 < C) { float v = row[c0]; a0 += v; q0 += v * v; }
        if (c1 < C) { float v = row[c1]; a1 += v; q1 += v * v; }
    }
    float* o1 = p1 + (size_t)blockIdx.x * 512;
    float* o2 = p2 + (size_t)blockIdx.x * 512;
    if (c0 < C) { o1[c0] = a0; o2[c0] = q0; }
    if (c1 < C) { o1[c1] = a1; o2[c1] = q1; }
}

__global__ void bn_finalize_kernel(const float* __restrict__ p1,
                                   const float* __restrict__ p2,
                                   int nblk, int M, int C,
                                   float* __restrict__ mean,
                                   float* __restrict__ istd)
{
    int warp = (blockIdx.x * blockDim.x + threadIdx.x) >> 5;
    int lane = threadIdx.x & 31;
    if (warp >= C) return;
    float s1 = 0.f, s2 = 0.f;
    for (int b = lane; b < nblk; b += 32) {
        s1 += p1[(size_t)b * 512 + warp];
        s2 += p2[(size_t)b * 512 + warp];
    }
    #pragma unroll
    for (int o = 16; o > 0; o >>= 1) {
        s1 += __shfl_down_sync(0xffffffffu, s1, o);
        s2 += __shfl_down_sync(0xffffffffu, s2, o);
    }
    if (lane == 0) {
        float m = s1 / (float)M;
        float v = s2 / (float)M - m * m;
        mean[warp] = m;
        istd[warp] = rsqrtf(v + 1e-5f);
    }
}

// mode 0: relu((a-m0)*i0); 1: relu(bn(a)+b); 2: relu(bn(a)+bn2(b))
__global__ void bn_apply_kernel(const float* __restrict__ a,
                                const float* __restrict__ b,
                                const float* __restrict__ m0, const float* __restrict__ i0,
                                const float* __restrict__ m1, const float* __restrict__ i1,
                                float* __restrict__ out, int M, int C, int mode)
{
    size_t i = (size_t)blockIdx.x * blockDim.x + threadIdx.x;
    size_t total = (size_t)M * C;
    if (i >= total) return;
    int c = (int)(i % (size_t)C);
    float v = (a[i] - m0[c]) * i0[c];
    if (mode == 1)      v += b[i];
    else if (mode == 2) v += (b[i] - m1[c]) * i1[c];
    out[i] = fmaxf(v, 0.f);
}

// ---------------- transposed conv ----------------------------------------
__global__ void deconv_kernel(const float* __restrict__ X,
                              const int* __restrict__ parent,
                              const int* __restrict__ koff,
                              const float* __restrict__ W,
                              float* __restrict__ out,
                              int M, int Cin, int Cout)
{
    __shared__ float xs[256];
    const int m = blockIdx.x;
    const int p = parent[m];
    const int o = koff[m];
    for (int c = threadIdx.x; c < Cin; c += blockDim.x)
        xs[c] = X[(size_t)p * Cin + c];
    __syncthreads();
    const float* Wk = W + (size_t)o * Cin * Cout;
    for (int n = threadIdx.x; n < Cout; n += blockDim.x) {
        float acc = 0.f;
        #pragma unroll 4
        for (int ci = 0; ci < Cin; ++ci)
            acc += xs[ci] * Wk[(size_t)ci * Cout + n];
        out[(size_t)m * Cout + n] = acc;
    }
}

__global__ void concat_kernel(const float* __restrict__ a, const float* __restrict__ b,
                              float* __restrict__ out, int M, int Ca, int Cb)
{
    size_t i = (size_t)blockIdx.x * blockDim.x + threadIdx.x;
    const int C = Ca + Cb;
    size_t total = (size_t)M * C;
    if (i >= total) return;
    int r = (int)(i / (size_t)C);
    int c = (int)(i % (size_t)C);
    out[i] = (c < Ca) ? a[(size_t)r * Ca + c] : b[(size_t)r * Cb + (c - Ca)];
}

// ---------------- host-side orchestration --------------------------------
static float *TA, *TB, *Y, *X0, *X1, *X2, *X3, *X4, *SPL, *P1, *P2, *MEAN, *ISTD;
static const float* gP;
static size_t gOff;

static inline const float* takeP(size_t n) { const float* w = gP + gOff; gOff += n; return w; }
static inline int cdiv(int a, int b) { return (a + b - 1) / b; }

static inline size_t gmma_smem(int TBN)
{
    int PB = TBN + 8;
    size_t floats = (size_t)2 * 64 * 36 + (size_t)2 * 32 * PB + 27 * 64;
    return floats * 4;
}

static void launch_gmma(int TBN, dim3 grid,
                        const float* X, const int* nbr, const float* W,
                        const float* bias, float* out,
                        int M, int Cin, int Cout, int K, int k0, int k1, int relu)
{
    size_t sh = gmma_smem(TBN);
    switch (TBN) {
    case 32: gmma_t<32><<<grid, 256, sh>>>(X, nbr, W, bias, out, M, Cin, Cout, K, k0, k1, relu); break;
    case 96: gmma_t<96><<<grid, 256, sh>>>(X, nbr, W, bias, out, M, Cin, Cout, K, k0, k1, relu); break;
    default: gmma_t<64><<<grid, 256, sh>>>(X, nbr, W, bias, out, M, Cin, Cout, K, k0, k1, relu); break;
    }
}

static void run_conv(const float* X, const int* nbr, const float* W, float* out,
                     int M, int Cin, int Cout, int K,
                     const float* bias = nullptr, int relu = 0)
{
    int TBN = (Cout == 96) ? 96 : (Cout <= 32 ? 32 : 64);
    dim3 grid(cdiv(Cout, TBN), cdiv(M, 64));
    int blocks = grid.x * grid.y;

    int S = 1, kper = K;
    if (nbr && K > 1 && blocks < 296) {
        S = (296 + blocks - 1) / blocks;
        if (S > K) S = K;
        kper = (K + S - 1) / S;
        S = (K + kper - 1) / kper;
    }
    if (S == 1) {
        launch_gmma(TBN, grid, X, nbr, W, bias, out, M, Cin, Cout, K, 0, K, relu);
    } else {
        long long MN = (long long)M * Cout;
        for (int s = 0; s < S; ++s) {
            int k0 = s * kper;
            int k1 = k0 + kper; if (k1 > K) k1 = K;
            launch_gmma(TBN, grid, X, nbr, W, nullptr, SPL + (size_t)s * MN,
                        M, Cin, Cout, K, k0, k1, 0);
        }
        reduce_split_kernel<<<(unsigned)((MN + 255) / 256), 256>>>(SPL, out, MN, S);
    }
}

static void run_bn(const float* a, int M, int C, int slot)
{
    int nb = cdiv(M, STAT_ROWS);
    bn_stats_kernel<<<nb, 256>>>(a, M, C, P1, P2);
    bn_finalize_kernel<<<cdiv(C * 32, 256), 256>>>(P1, P2, nb, M, C,
                                                   MEAN + slot * 512, ISTD + slot * 512);
}

static void run_apply(const float* a, const float* b, float* out, int M, int C, int mode)
{
    size_t total = (size_t)M * C;
    bn_apply_kernel<<<(unsigned)((total + 255) / 256), 256>>>(
        a, b, MEAN, ISTD, MEAN + 512, ISTD + 512, out, M, C, mode);
}

static void cbr(const float* x, const int* nbr, int M, int Cin, int Cout, int K, float* out)
{
    const float* w = takeP((size_t)K * Cin * Cout);
    run_conv(x, nbr, w, TA, M, Cin, Cout, K);
    run_bn(TA, M, Cout, 0);
    run_apply(TA, nullptr, out, M, Cout, 0);
}

static void resblock(const float* x, const int* nbr, int M, int ci, int co, float* out)
{
    const float* w1 = takeP((size_t)27 * ci * co);
    const float* w2 = takeP((size_t)27 * co * co);
    run_conv(x, nbr, w1, TA, M, ci, co, 27);
    run_bn(TA, M, co, 0);
    run_apply(TA, nullptr, TB, M, co, 0);
    run_conv(TB, nbr, w2, TA, M, co, co, 27);
    run_bn(TA, M, co, 0);
    if (ci != co) {
        const float* ws = takeP((size_t)ci * co);
        run_conv(x, nullptr, ws, TB, M, ci, co, 1);
        run_bn(TB, M, co, 1);
        run_apply(TA, TB, out, M, co, 2);
    } else {
        run_apply(TA, x, out, M, co, 1);
    }
}

static void up_block(const float* x, const int* par, const int* off, int M,
                     int Cin, int Cout, const float* skip, int Cskip, float* out)
{
    const float* w = takeP((size_t)8 * Cin * Cout);
    deconv_kernel<<<M, 128>>>(x, par, off, w, TA, M, Cin, Cout);
    run_bn(TA, M, Cout, 0);
    run_apply(TA, nullptr, TB, M, Cout, 0);
    size_t total = (size_t)M * (Cout + Cskip);
    concat_kernel<<<(unsigned)((total + 255) / 256), 256>>>(TB, skip, out, M, Cout, Cskip);
}

extern "C" void kernel_launch(void* const* d_in, const int* in_sizes, int n_in,
                              void* d_out, int out_size)
{
    const float* x    = (const float*)d_in[0];
    const int* nbr0   = (const int*)d_in[1];
    const int* nbr1   = (const int*)d_in[2];
    const int* nbr2   = (const int*)d_in[3];
    const int* nbr3   = (const int*)d_in[4];
    const int* nbr4   = (const int*)d_in[5];
    const int* d1     = (const int*)d_in[6];
    const int* d2     = (const int*)d_in[7];
    const int* d3     = (const int*)d_in[8];
    const int* d4     = (const int*)d_in[9];
    const int* u1p    = (const int*)d_in[10];
    const int* u1o    = (const int*)d_in[11];
    const int* u2p    = (const int*)d_in[12];
    const int* u2o    = (const int*)d_in[13];
    const int* u3p    = (const int*)d_in[14];
    const int* u3o    = (const int*)d_in[15];
    const int* u4p    = (const int*)d_in[16];
    const int* u4o    = (const int*)d_in[17];
    gP = (const float*)d_in[18];
    gOff = 0;

    // allow >48KB dynamic smem (needed for TBN=96; harmless otherwise)
    cudaFuncSetAttribute((const void*)gmma_t<32>,
                         cudaFuncAttributeMaxDynamicSharedMemorySize, 65536);
    cudaFuncSetAttribute((const void*)gmma_t<64>,
                         cudaFuncAttributeMaxDynamicSharedMemorySize, 65536);
    cudaFuncSetAttribute((const void*)gmma_t<96>,
                         cudaFuncAttributeMaxDynamicSharedMemorySize, 65536);

    cudaGetSymbolAddress((void**)&X0,   g_x0);
    cudaGetSymbolAddress((void**)&X1,   g_x1);
    cudaGetSymbolAddress((void**)&X2,   g_x2);
    cudaGetSymbolAddress((void**)&X3,   g_x3);
    cudaGetSymbolAddress((void**)&X4,   g_x4);
    cudaGetSymbolAddress((void**)&Y,    g_y);
    cudaGetSymbolAddress((void**)&TA,   g_ta);
    cudaGetSymbolAddress((void**)&TB,   g_tb);
    cudaGetSymbolAddress((void**)&SPL,  g_split);
    cudaGetSymbolAddress((void**)&P1,   g_p1);
    cudaGetSymbolAddress((void**)&P2,   g_p2);
    cudaGetSymbolAddress((void**)&MEAN, g_mean);
    cudaGetSymbolAddress((void**)&ISTD, g_istd);

    // ---- stem (N0) ----
    cbr(x,  nbr0, NN0, 4,  32, 27, X0);
    cbr(X0, nbr0, NN0, 32, 32, 27, X0);

    // ---- stage1 (N1) ----
    cbr(X0, d1, NN1, 32, 32, 8, Y);
    resblock(Y, nbr1, NN1, 32, 32, Y);
    resblock(Y, nbr1, NN1, 32, 32, X1);

    // ---- stage2 (N2) ----
    cbr(X1, d2, NN2, 32, 32, 8, Y);
    resblock(Y, nbr2, NN2, 32, 64, Y);
    resblock(Y, nbr2, NN2, 64, 64, X2);

    // ---- stage3 (N3) ----
    cbr(X2, d3, NN3, 64, 64, 8, Y);
    resblock(Y, nbr3, NN3, 64, 128, Y);
    resblock(Y, nbr3, NN3, 128, 128, X3);

    // ---- stage4 (N4) ----
    cbr(X3, d4, NN4, 128, 128, 8, Y);
    resblock(Y, nbr4, NN4, 128, 256, Y);
    resblock(Y, nbr4, NN4, 256, 256, X4);

    // ---- up1 (N3) ----
    up_block(X4, u1p, u1o, NN3, 256, 256, X3, 128, Y);
    resblock(Y, nbr3, NN3, 384, 256, Y);
    resblock(Y, nbr3, NN3, 256, 256, Y);

    // ---- up2 (N2) ----
    up_block(Y, u2p, u2o, NN2, 256, 128, X2, 64, Y);
    resblock(Y, nbr2, NN2, 192, 128, Y);
    resblock(Y, nbr2, NN2, 128, 128, Y);

    // ---- up3 (N1) ----
    up_block(Y, u3p, u3o, NN1, 128, 96, X1, 32, Y);
    resblock(Y, nbr1, NN1, 128, 96, Y);
    resblock(Y, nbr1, NN1, 96, 96, Y);

    // ---- up4 (N0) ----
    up_block(Y, u4p, u4o, NN0, 96, 96, X0, 32, Y);
    resblock(Y, nbr0, NN0, 128, 96, Y);
    resblock(Y, nbr0, NN0, 96, 96, Y);

    // ---- head ----
    const float* wc = takeP((size_t)96 * 19);
    const float* bc = takeP(19);
    const float* w1 = takeP((size_t)96 * 96);
    const float* b1 = takeP(96);
    const float* w2 = takeP((size_t)96 * 128);
    const float* b2 = takeP(128);

    float* out = (float*)d_out;
    run_conv(Y, nullptr, wc, out, NN0, 96, 19, 1, bc, 0);
    run_conv(Y,  nullptr, w1, TA, NN0, 96, 96, 1, b1, 1);
    run_conv(TA, nullptr, w2, out + (size_t)NN0 * 19, NN0, 96, 128, 1, b2, 0);
}